// round 10
// baseline (speedup 1.0000x reference)
#include <cuda_runtime.h>
#include <stdint.h>

// N=100000, W=32, D=32. Output row = 1088 floats = 4352 bytes.
// Per row i: [ gathered x rows (4096 B) | dis (128 B) | angle (128 B) ]
// Warp handles TWO rows, R8 front-batched structure, but ALL payload moves
// use 256-bit (v8.f32) loads/stores: one x row = 4 lanes x 32B, so each
// warp instruction covers 8 neighbor rows (1024B) -> half the L1tex
// wavefronts of the float4 version at identical byte traffic.

#define ROW_F4 272

struct F8 { float4 lo, hi; };

__device__ __forceinline__ F8 ldg256(const void* p) {
    F8 r;
    asm volatile("ld.global.cg.v8.f32 {%0,%1,%2,%3,%4,%5,%6,%7}, [%8];"
        : "=f"(r.lo.x), "=f"(r.lo.y), "=f"(r.lo.z), "=f"(r.lo.w),
          "=f"(r.hi.x), "=f"(r.hi.y), "=f"(r.hi.z), "=f"(r.hi.w)
        : "l"(p));
    return r;
}

__device__ __forceinline__ void stg256(void* p, const F8& v) {
    asm volatile("st.global.cs.v8.f32 [%0], {%1,%2,%3,%4,%5,%6,%7,%8};"
        :: "l"(p),
           "f"(v.lo.x), "f"(v.lo.y), "f"(v.lo.z), "f"(v.lo.w),
           "f"(v.hi.x), "f"(v.hi.y), "f"(v.hi.z), "f"(v.hi.w)
        : "memory");
}

__global__ __launch_bounds__(256)
void fused_gather_concat_v8_kernel(const void* __restrict__ xraw,
                                   const void* __restrict__ idx,
                                   const void* __restrict__ disraw,
                                   const void* __restrict__ angraw,
                                   void* __restrict__ outraw,
                                   int n_rows)
{
    const int warp_id = (blockIdx.x * blockDim.x + threadIdx.x) >> 5;
    const int lane    = threadIdx.x & 31;

    // Dtype detection (values < 100000: little-endian int64 => all odd
    // 32-bit words are 0; 32 random i32 all-zero: p ~ 1e-160). Broadcast.
    const int probe = __ldg((const int*)idx + 2 * lane + 1);
    const bool is64 = (__ballot_sync(0xffffffffu, probe != 0) == 0u);

    const int i0 = warp_id * 2;
    const int i1 = i0 + 1;
    if (i0 >= n_rows) return;
    const bool has1 = (i1 < n_rows);

    // ── Front batch: idx loads (coalesced, read-once) ──
    int ja, jb = 0;
    if (is64) {
        ja = (int)__ldcs((const long long*)idx + (long long)i0 * 32 + lane);
        if (has1) jb = (int)__ldcs((const long long*)idx + (long long)i1 * 32 + lane);
    } else {
        ja = __ldcs((const int*)idx + i0 * 32 + lane);
        if (has1) jb = __ldcs((const int*)idx + i1 * 32 + lane);
    }

    // ── Front batch: tail payload (dis|angle, 256B per row = 8 lanes) ──
    // lanes 0-7 -> row i0, lanes 8-15 -> row i1. 256-bit loads.
    F8 tv;
    {
        const int li = (lane < 8) ? i0 : i1;
        const int lr = lane & 7;
        if (lane < 8 || (lane < 16 && has1)) {
            const char* src = (lr < 4)
                ? (const char*)disraw + (long long)li * 128 + lr * 32
                : (const char*)angraw + (long long)li * 128 + (lr - 4) * 32;
            tv = ldg256(src);
        }
    }

    const int wbase = lane >> 2;   // neighbor sub-slot within instruction (0..7)
    const int seg   = lane & 3;    // 32B chunk within the 128B x row

    // Distribute needed neighbor indices: instruction 'it' covers
    // neighbors it*8 .. it*8+7; lane handles neighbor it*8 + (lane>>2).
    int jwa[4], jwb[4];
#pragma unroll
    for (int it = 0; it < 4; it++) {
        jwa[it] = __shfl_sync(0xffffffffu, ja, it * 8 + wbase);
        jwb[it] = __shfl_sync(0xffffffffu, jb, it * 8 + wbase);
    }

    // ── 8 independent 256-bit gathers (4 per row; 1024B each) ──
    const char* xb = (const char*)xraw;
    F8 va[4], vb[4];
#pragma unroll
    for (int it = 0; it < 4; it++)
        va[it] = ldg256(xb + (long long)jwa[it] * 128 + seg * 32);
    if (has1) {
#pragma unroll
        for (int it = 0; it < 4; it++)
            vb[it] = ldg256(xb + (long long)jwb[it] * 128 + seg * 32);
    }

    // ── Coalesced 256-bit streaming stores ──
    char* ob0 = (char*)outraw + (long long)i0 * (ROW_F4 * 16);
#pragma unroll
    for (int it = 0; it < 4; it++)
        stg256(ob0 + it * 1024 + lane * 32, va[it]);
    if (has1) {
        char* ob1 = (char*)outraw + (long long)i1 * (ROW_F4 * 16);
#pragma unroll
        for (int it = 0; it < 4; it++)
            stg256(ob1 + it * 1024 + lane * 32, vb[it]);
        // Tail stores: lanes 0-7 -> row0 [dis|angle], lanes 8-15 -> row1.
        if (lane < 8)       stg256(ob0 + 4096 + lane * 32, tv);
        else if (lane < 16) stg256(ob1 + 4096 + (lane - 8) * 32, tv);
    } else {
        if (lane < 8)       stg256(ob0 + 4096 + lane * 32, tv);
    }
}

extern "C" void kernel_launch(void* const* d_in, const int* in_sizes, int n_in,
                              void* d_out, int out_size)
{
    const void* x    = d_in[0];
    const void* idx  = d_in[1];
    const void* dis  = d_in[2];
    const void* ang  = d_in[3];

    const int n_rows = in_sizes[0] / 32;   // N

    const int threads = 256;                        // 8 warps/block
    const int rows_per_block = 16;                  // 2 rows per warp
    const int blocks = (n_rows + rows_per_block - 1) / rows_per_block;
    fused_gather_concat_v8_kernel<<<blocks, threads>>>(x, idx, dis, ang,
                                                       d_out, n_rows);
}

// round 11
// speedup vs baseline: 1.0255x; 1.0255x over previous
#include <cuda_runtime.h>
#include <stdint.h>

// N=100000, W=32, D=32. Output row = 1088 floats = 272 float4.
// Per row i: [ gathered x rows (256 f4) | dis (8 f4) | angle (8 f4) ]
// Warp handles TWO rows; ALL loads (2 idx, 16 gathers, tail) front-batched
// then all stores. At the DRAM write-bandwidth floor (~435MB @ ~5.75TB/s).
// Fast path assumes n_rows % 16 == 0 (true for N=100000); generic kernel
// covers the remainder otherwise.

#define ROW_F4 272

__device__ __forceinline__ void process_two_rows(
    const float4* __restrict__ x4, const void* __restrict__ idx,
    const float4* __restrict__ dis4, const float4* __restrict__ ang4,
    float4* __restrict__ out4, int i0, bool is64, int lane)
{
    const int i1 = i0 + 1;

    // idx loads: one element per lane per row (coalesced, read-once).
    int ja, jb;
    if (is64) {
        ja = (int)__ldcs((const long long*)idx + (long long)i0 * 32 + lane);
        jb = (int)__ldcs((const long long*)idx + (long long)i1 * 32 + lane);
    } else {
        ja = __ldcs((const int*)idx + i0 * 32 + lane);
        jb = __ldcs((const int*)idx + i1 * 32 + lane);
    }

    // Tail payload (independent of idx): rides the front batch.
    // lanes 0-15 -> row i0 [dis|angle], lanes 16-31 -> row i1.
    const int li = (lane < 16) ? i0 : i1;
    const int lr = lane & 15;
    float4 tv;
    if (lr < 8) tv = __ldcs(dis4 + li * 8 + lr);
    else        tv = __ldcs(ang4 + li * 8 + (lr - 8));

    const int wbase = lane >> 3;   // lane-group (0..3)
    const int seg   = lane & 7;    // float4 within the 32-float x row

    int jwa[8], jwb[8];
#pragma unroll
    for (int it = 0; it < 8; it++) {
        jwa[it] = __shfl_sync(0xffffffffu, ja, it * 4 + wbase);
        jwb[it] = __shfl_sync(0xffffffffu, jb, it * 4 + wbase);
    }

    // 16 independent gathers (MLP=16+tail). .cg: 12.8MB random working set
    // cannot live in L1 -> skip L1 allocate.
    float4 va[8], vb[8];
#pragma unroll
    for (int it = 0; it < 8; it++)
        va[it] = __ldcg(x4 + (long long)jwa[it] * 8 + seg);
#pragma unroll
    for (int it = 0; it < 8; it++)
        vb[it] = __ldcg(x4 + (long long)jwb[it] * 8 + seg);

    // Coalesced streaming stores (output never re-read).
    float4* __restrict__ orow0 = out4 + (long long)i0 * ROW_F4;
    float4* __restrict__ orow1 = out4 + (long long)i1 * ROW_F4;
#pragma unroll
    for (int it = 0; it < 8; it++)
        __stcs(orow0 + it * 32 + lane, va[it]);
#pragma unroll
    for (int it = 0; it < 8; it++)
        __stcs(orow1 + it * 32 + lane, vb[it]);

    if (lane < 16) __stcs(orow0 + 256 + lane, tv);
    else           __stcs(orow1 + 256 + (lane - 16), tv);
}

// Fast path: every warp has exactly two full rows (n_rows % 16 == 0).
__global__ __launch_bounds__(256)
void fused_gather_concat_even_kernel(const float4* __restrict__ x4,
                                     const void*  __restrict__ idx,
                                     const float4* __restrict__ dis4,
                                     const float4* __restrict__ ang4,
                                     float4* __restrict__ out4)
{
    const int warp_id = (blockIdx.x * blockDim.x + threadIdx.x) >> 5;
    const int lane    = threadIdx.x & 31;

    // Dtype detection (values < 100000: little-endian int64 => all odd
    // 32-bit words are 0; 32 random i32 all-zero: p ~ 1e-160). Broadcast.
    const int probe = __ldg((const int*)idx + 2 * lane + 1);
    const bool is64 = (__ballot_sync(0xffffffffu, probe != 0) == 0u);

    process_two_rows(x4, idx, dis4, ang4, out4, warp_id * 2, is64, lane);
}

// Generic path (any n_rows): bounds-checked single/double row per warp.
__global__ __launch_bounds__(256)
void fused_gather_concat_gen_kernel(const float4* __restrict__ x4,
                                    const void*  __restrict__ idx,
                                    const float4* __restrict__ dis4,
                                    const float4* __restrict__ ang4,
                                    float4* __restrict__ out4,
                                    int n_rows)
{
    const int warp_id = (blockIdx.x * blockDim.x + threadIdx.x) >> 5;
    const int lane    = threadIdx.x & 31;

    const int probe = __ldg((const int*)idx + 2 * lane + 1);
    const bool is64 = (__ballot_sync(0xffffffffu, probe != 0) == 0u);

    const int i0 = warp_id * 2;
    if (i0 >= n_rows) return;

    if (i0 + 1 < n_rows) {
        process_two_rows(x4, idx, dis4, ang4, out4, i0, is64, lane);
        return;
    }

    // Single trailing row.
    int ji;
    if (is64) ji = (int)__ldcs((const long long*)idx + (long long)i0 * 32 + lane);
    else      ji = __ldcs((const int*)idx + i0 * 32 + lane);

    const int wbase = lane >> 3;
    const int seg   = lane & 7;
    int jw[8];
#pragma unroll
    for (int it = 0; it < 8; it++)
        jw[it] = __shfl_sync(0xffffffffu, ji, it * 4 + wbase);

    float4 v[8];
#pragma unroll
    for (int it = 0; it < 8; it++)
        v[it] = __ldcg(x4 + (long long)jw[it] * 8 + seg);

    float4* __restrict__ orow = out4 + (long long)i0 * ROW_F4;
#pragma unroll
    for (int it = 0; it < 8; it++)
        __stcs(orow + it * 32 + lane, v[it]);

    if (lane < 8)
        __stcs(orow + 256 + lane, __ldcs(dis4 + i0 * 8 + lane));
    else if (lane < 16)
        __stcs(orow + 256 + lane, __ldcs(ang4 + i0 * 8 + (lane - 8)));
}

extern "C" void kernel_launch(void* const* d_in, const int* in_sizes, int n_in,
                              void* d_out, int out_size)
{
    const float4* x4   = (const float4*)d_in[0];
    const void*   idx  = d_in[1];
    const float4* dis4 = (const float4*)d_in[2];
    const float4* ang4 = (const float4*)d_in[3];
    float4* out4 = (float4*)d_out;

    const int n_rows = in_sizes[0] / 32;   // N

    const int threads = 256;               // 8 warps/block, 2 rows/warp
    if ((n_rows & 15) == 0) {
        const int blocks = n_rows / 16;
        fused_gather_concat_even_kernel<<<blocks, threads>>>(x4, idx, dis4,
                                                             ang4, out4);
    } else {
        const int blocks = (n_rows + 15) / 16;
        fused_gather_concat_gen_kernel<<<blocks, threads>>>(x4, idx, dis4,
                                                            ang4, out4, n_rows);
    }
}

// round 12
// speedup vs baseline: 1.0814x; 1.0546x over previous
#include <cuda_runtime.h>
#include <stdint.h>

// N=100000, W=32, D=32. Output row = 1088 floats = 272 float4.
// Per row i: [ gathered x rows (256 f4) | dis (8 f4) | angle (8 f4) ]
// Warp handles TWO rows; ALL loads (2 idx, 16 gathers, tail) front-batched
// for max MLP, then all stores. At the DRAM-write floor (~435MB mandatory).
// This is the R8 champion kernel, restored verbatim.

#define ROW_F4 272

__global__ __launch_bounds__(256)
void fused_gather_concat_warp2_kernel(const float4* __restrict__ x4,
                                      const void*  __restrict__ idx,
                                      const float4* __restrict__ dis4,
                                      const float4* __restrict__ ang4,
                                      float4* __restrict__ out4,
                                      int n_rows)
{
    const int warp_id = (blockIdx.x * blockDim.x + threadIdx.x) >> 5;
    const int lane    = threadIdx.x & 31;

    // Dtype detection (values < 100000: little-endian int64 => all odd
    // 32-bit words are 0; 32 random i32 all-zero: p ~ 1e-160). Broadcast.
    const int probe = __ldg((const int*)idx + 2 * lane + 1);
    const bool is64 = (__ballot_sync(0xffffffffu, probe != 0) == 0u);

    const int i0 = warp_id * 2;
    const int i1 = i0 + 1;
    if (i0 >= n_rows) return;
    const bool has1 = (i1 < n_rows);

    // idx loads: one element per lane per row (coalesced, read-once).
    int ja, jb = 0;
    if (is64) {
        ja = (int)__ldcs((const long long*)idx + (long long)i0 * 32 + lane);
        if (has1) jb = (int)__ldcs((const long long*)idx + (long long)i1 * 32 + lane);
    } else {
        ja = __ldcs((const int*)idx + i0 * 32 + lane);
        if (has1) jb = __ldcs((const int*)idx + i1 * 32 + lane);
    }

    // Tail payload (independent of idx): issue early so it rides the batch.
    float4 tv0, tv1;
    {
        const int li = (lane < 16) ? i0 : i1;
        const int lr = lane & 15;
        const bool lv = (lane < 16) || has1;
        if (lv) {
            if (lr < 8) tv0 = __ldcs(dis4 + li * 8 + lr);
            else        tv0 = __ldcs(ang4 + li * 8 + (lr - 8));
        }
        (void)tv1;
    }

    const int wbase = lane >> 3;   // lane-group (0..3)
    const int seg   = lane & 7;    // float4 within the 32-float x row

    // Distribute needed neighbor indices via shuffle.
    int jwa[8], jwb[8];
#pragma unroll
    for (int it = 0; it < 8; it++) {
        jwa[it] = __shfl_sync(0xffffffffu, ja, it * 4 + wbase);
        jwb[it] = __shfl_sync(0xffffffffu, jb, it * 4 + wbase);
    }

    // 16 independent gathers (MLP=16+tail). .cg: skip L1 allocate (random
    // 12.8MB working set cannot live in 228KB L1).
    float4 va[8], vb[8];
#pragma unroll
    for (int it = 0; it < 8; it++)
        va[it] = __ldcg(x4 + (long long)jwa[it] * 8 + seg);
    if (has1) {
#pragma unroll
        for (int it = 0; it < 8; it++)
            vb[it] = __ldcg(x4 + (long long)jwb[it] * 8 + seg);
    }

    // Coalesced streaming stores (output never re-read).
    float4* __restrict__ orow0 = out4 + (long long)i0 * ROW_F4;
#pragma unroll
    for (int it = 0; it < 8; it++)
        __stcs(orow0 + it * 32 + lane, va[it]);
    if (has1) {
        float4* __restrict__ orow1 = out4 + (long long)i1 * ROW_F4;
#pragma unroll
        for (int it = 0; it < 8; it++)
            __stcs(orow1 + it * 32 + lane, vb[it]);

        // Packed tail store: lanes 0-15 -> row0, lanes 16-31 -> row1.
        if (lane < 16) __stcs(orow0 + 256 + lane, tv0);
        else           __stcs(orow1 + 256 + (lane - 16), tv0);
    } else {
        if (lane < 16) __stcs(orow0 + 256 + lane, tv0);
    }
}

extern "C" void kernel_launch(void* const* d_in, const int* in_sizes, int n_in,
                              void* d_out, int out_size)
{
    const float4* x4   = (const float4*)d_in[0];
    const void*   idx  = d_in[1];
    const float4* dis4 = (const float4*)d_in[2];
    const float4* ang4 = (const float4*)d_in[3];
    float4* out4 = (float4*)d_out;

    const int n_rows = in_sizes[0] / 32;   // N

    const int threads = 256;                        // 8 warps/block
    const int rows_per_block = 16;                  // 2 rows per warp
    const int blocks = (n_rows + rows_per_block - 1) / rows_per_block;
    fused_gather_concat_warp2_kernel<<<blocks, threads>>>(x4, idx, dis4, ang4,
                                                          out4, n_rows);
}